// round 15
// baseline (speedup 1.0000x reference)
#include <cuda_runtime.h>
#include <cuda_fp16.h>
#include <math.h>
#include <stdint.h>

#define BB 4
#define SS 2048
#define EE 1024

#define NBS ((size_t)BB * SS * EE)   // 8388608
#define NW  ((size_t)EE * EE)        // 1048576
#define NP  ((size_t)BB * SS * SS)   // 16777216

// ---------------------------------------------------------------------------
// Scratch (__device__ globals) — contiguous slabs so grid.z can stride
// ---------------------------------------------------------------------------
__device__ __align__(256) __half g_in[3 * NBS];    // fp16 inputs   (q,k,v slabs)
__device__ __align__(256) __half g_wt[3 * NW];     // fp16 W^T      (q,k,v slabs)
__device__ __align__(256) float  g_bias[3 * EE];   // fp32 biases   (q,k,v slabs)
__device__ __align__(256) __half g_qkv[3 * NBS];   // fp16 q,k,v projections
__device__ __align__(256) __half g_ph[NP];         // fp16 scores -> probs (in-place)

struct Src3 { const float* p0; const float* p1; const float* p2; };

// ---------------------------------------------------------------------------
// Baseline-PTX primitives (compute_103-safe)
// ---------------------------------------------------------------------------
__device__ __forceinline__ uint32_t smem_u32(const void* p) {
    uint32_t a;
    asm("{ .reg .u64 t; cvta.to.shared.u64 t, %1; cvt.u32.u64 %0, t; }"
        : "=r"(a) : "l"(p));
    return a;
}

__device__ __forceinline__ void cp_async16(uint32_t s, const void* g) {
    asm volatile("cp.async.cg.shared.global [%0], [%1], 16;" :: "r"(s), "l"(g));
}
__device__ __forceinline__ void cp_commit() {
    asm volatile("cp.async.commit_group;" ::: "memory");
}
__device__ __forceinline__ void cp_wait1() {
    asm volatile("cp.async.wait_group 1;" ::: "memory");
}

__device__ __forceinline__ void ldsm4(uint32_t* r, uint32_t addr) {
    asm volatile("ldmatrix.sync.aligned.m8n8.x4.shared.b16 {%0,%1,%2,%3}, [%4];"
        : "=r"(r[0]), "=r"(r[1]), "=r"(r[2]), "=r"(r[3]) : "r"(addr));
}
__device__ __forceinline__ void ldsm4t(uint32_t* r, uint32_t addr) {
    asm volatile("ldmatrix.sync.aligned.m8n8.x4.trans.shared.b16 {%0,%1,%2,%3}, [%4];"
        : "=r"(r[0]), "=r"(r[1]), "=r"(r[2]), "=r"(r[3]) : "r"(addr));
}

__device__ __forceinline__ void mma16816(float* c, const uint32_t* a,
                                         const uint32_t* b) {
    asm volatile(
        "mma.sync.aligned.m16n8k16.row.col.f32.f16.f16.f32 "
        "{%0,%1,%2,%3}, {%4,%5,%6,%7}, {%8,%9}, {%0,%1,%2,%3};"
        : "+f"(c[0]), "+f"(c[1]), "+f"(c[2]), "+f"(c[3])
        : "r"(a[0]), "r"(a[1]), "r"(a[2]), "r"(a[3]), "r"(b[0]), "r"(b[1]));
}

// ---------------------------------------------------------------------------
// HMMA fp16 GEMM, 2 CTAs/SM, fragment-double-buffered inner loop.
//   TRANS_B = false: C = alpha*(A[M,K] @ B[N,K]^T)+bias  (B K-major)
//   TRANS_B = true : C = alpha*(A[M,K] @ B[K,N])+bias    (B N-major, e.g. V[S,E])
//   CTA 128x128, BK=64, 8 warps (2x4), warp tile 64x32, 3-stage cp.async.
//   OUT_MODE: 0 = fp32, 2 = fp16
// ---------------------------------------------------------------------------
#define ROWH 72                           // K-major pitch: 64 + 8 pad halves
#define TBPITCH 136                       // N-major pitch: 128 + 8 pad halves
#define TILE_A (128 * ROWH * 2)           // 18432 B
#define TILE_BK (128 * ROWH * 2)          // 18432 B
#define TILE_BT (64 * TBPITCH * 2)        // 17408 B

template <int OUT_MODE, bool HAS_BIAS, bool TRANS_B>
__global__ __launch_bounds__(256, 2)
void hgemm(const __half* __restrict__ A, const __half* __restrict__ B,
           const float* __restrict__ bias,
           float* __restrict__ Cf, __half* __restrict__ Ch,
           int M, int N, int K,
           long long sA, long long sB, long long sC,
           int biasStride, float alpha)
{
    constexpr int TILE_BSZ = TRANS_B ? TILE_BT : TILE_BK;
    constexpr int STAGE = TILE_A + TILE_BSZ;
    extern __shared__ __half sm[];
    const uint32_t sbase = smem_u32(sm);

    const int tid  = threadIdx.x;
    const int lane = tid & 31;
    const int wid  = tid >> 5;
    const int wm   = (wid >> 2) * 64;      // 0,64
    const int wn   = (wid & 3) * 32;       // 0..96

    const int n0 = blockIdx.x * 128;
    const int m0 = blockIdx.y * 128;

    A += (size_t)blockIdx.z * sA;
    B += (size_t)blockIdx.z * sB;
    if (HAS_BIAS) bias += (size_t)blockIdx.z * biasStride;

    const int nch = K >> 6;                // BK = 64

    auto issue_stage = [&](int c, int buf) {
        const int kt = c << 6;
        const uint32_t st = (uint32_t)buf * STAGE;
        // A: 128 rows x 8 chunks = 1024 chunks, 4/thread
#pragma unroll
        for (int it = 0; it < 4; ++it) {
            const int i = it * 256 + tid;
            const int r  = i >> 3;
            const int cm = i & 7;
            const __half* g = A + (size_t)(m0 + r) * K + kt + cm * 8;
            const uint32_t s = sbase + st + (uint32_t)r * (ROWH * 2)
                             + (uint32_t)cm * 16;
            cp_async16(s, g);
        }
        if (!TRANS_B) {
            // B: 128 n-rows x 8 chunks = 1024 chunks, 4/thread
#pragma unroll
            for (int it = 0; it < 4; ++it) {
                const int i = it * 256 + tid;
                const int r  = i >> 3;
                const int cm = i & 7;
                const __half* g = B + (size_t)(n0 + r) * K + kt + cm * 8;
                const uint32_t s = sbase + st + (uint32_t)TILE_A
                                 + (uint32_t)r * (ROWH * 2) + (uint32_t)cm * 16;
                cp_async16(s, g);
            }
        } else {
            // B: 64 k-rows x 16 chunks = 1024 chunks, 4/thread
#pragma unroll
            for (int it = 0; it < 4; ++it) {
                const int i = it * 256 + tid;
                const int r  = i >> 4;
                const int cm = i & 15;
                const __half* g = B + (size_t)(kt + r) * N + n0 + cm * 8;
                const uint32_t s = sbase + st + (uint32_t)TILE_A
                                 + (uint32_t)r * (TBPITCH * 2) + (uint32_t)cm * 16;
                cp_async16(s, g);
            }
        }
        cp_commit();
    };

    float acc[4][4][4];
#pragma unroll
    for (int i = 0; i < 4; ++i)
#pragma unroll
        for (int j = 0; j < 4; ++j)
#pragma unroll
            for (int q = 0; q < 4; ++q) acc[i][j][q] = 0.f;

    issue_stage(0, 0);
    issue_stage(1, 1);

    // fragment double buffers
    uint32_t ah[2][4][4];
    uint32_t bh[2][2][4];

    for (int c = 0; c < nch; ++c) {
        cp_wait1();
        __syncthreads();

        if (c + 2 < nch) issue_stage(c + 2, (c + 2) % 3);
        else             cp_commit();   // keep group counts aligned

        const uint32_t st = (uint32_t)(c % 3) * STAGE;
        const uint32_t sA_ = sbase + st;
        const uint32_t sB_ = sA_ + TILE_A;

        // per-thread invariant address components
        const uint32_t aAddr = sA_ + (uint32_t)(wm + (lane & 15)) * (ROWH * 2)
                             + (uint32_t)((lane >> 4) << 3) * 2;
        uint32_t bAddrK = 0, bAddrT = 0;
        if (!TRANS_B)
            bAddrK = sB_ + (uint32_t)(wn + ((lane >> 4) << 3) + (lane & 7)) * (ROWH * 2)
                   + (uint32_t)(((lane >> 3) & 1) << 3) * 2;
        else
            bAddrT = sB_ + (uint32_t)((((lane >> 3) & 1) << 3) + (lane & 7)) * (TBPITCH * 2)
                   + (uint32_t)(wn + ((lane >> 4) << 3)) * 2;

        auto load_a = [&](int buf, int ks) {
#pragma unroll
            for (int mi = 0; mi < 4; ++mi)
                ldsm4(ah[buf][mi], aAddr + (uint32_t)(mi * 16) * (ROWH * 2)
                                         + (uint32_t)ks * 2);
        };
        auto load_b = [&](int buf, int ks) {
            if (!TRANS_B) {
#pragma unroll
                for (int nb = 0; nb < 2; ++nb)
                    ldsm4(bh[buf][nb], bAddrK + (uint32_t)(nb * 16) * (ROWH * 2)
                                              + (uint32_t)ks * 2);
            } else {
#pragma unroll
                for (int nb = 0; nb < 2; ++nb)
                    ldsm4t(bh[buf][nb], bAddrT + (uint32_t)ks * (TBPITCH * 2)
                                               + (uint32_t)(nb * 16) * 2);
            }
        };

        load_a(0, 0);
        load_b(0, 0);

#pragma unroll
        for (int s = 0; s < 4; ++s) {
            const int cur = s & 1;
            const int nxt = cur ^ 1;
            if (s < 3) {                // prefetch next ks-step's fragments
                load_a(nxt, (s + 1) * 16);
                load_b(nxt, (s + 1) * 16);
            }
#pragma unroll
            for (int mi = 0; mi < 4; ++mi)
#pragma unroll
                for (int nf = 0; nf < 4; ++nf)
                    mma16816(acc[mi][nf], ah[cur][mi],
                             &bh[cur][nf >> 1][(nf & 1) << 1]);
        }
    }

    // ---- epilogue: each warp writes 64x32 ----
    const long long cbo = (long long)blockIdx.z * sC;
#pragma unroll
    for (int mi = 0; mi < 4; ++mi) {
        const int r0 = m0 + wm + mi * 16 + (lane >> 2);
#pragma unroll
        for (int nf = 0; nf < 4; ++nf) {
            const int col = n0 + wn + nf * 8 + (lane & 3) * 2;
            float b0 = 0.f, b1 = 0.f;
            if (HAS_BIAS) { b0 = __ldg(&bias[col]); b1 = __ldg(&bias[col + 1]); }
            const float v0 = acc[mi][nf][0] * alpha + b0;
            const float v1 = acc[mi][nf][1] * alpha + b1;
            const float v2 = acc[mi][nf][2] * alpha + b0;
            const float v3 = acc[mi][nf][3] * alpha + b1;
            const long long o0 = cbo + (long long)r0 * N + col;
            const long long o1 = o0 + 8LL * N;
            if (OUT_MODE == 0) {
                *reinterpret_cast<float2*>(Cf + o0) = make_float2(v0, v1);
                *reinterpret_cast<float2*>(Cf + o1) = make_float2(v2, v3);
            } else {
                *reinterpret_cast<__half2*>(Ch + o0) =
                    __halves2half2(__float2half_rn(v0), __float2half_rn(v1));
                *reinterpret_cast<__half2*>(Ch + o1) =
                    __halves2half2(__float2half_rn(v2), __float2half_rn(v3));
            }
        }
    }
}

#define SMEM_GEMM_K (3 * (TILE_A + TILE_BK))   // 110592 B
#define SMEM_GEMM_T (3 * (TILE_A + TILE_BT))   // 107520 B

// ---------------------------------------------------------------------------
// fp32 -> fp16 convert, 3 tensors in one launch (grid.z)
// ---------------------------------------------------------------------------
__global__ __launch_bounds__(256)
void convert3_kernel(Src3 src, __half* __restrict__ dst, size_t n)
{
    const float* in = (blockIdx.z == 0) ? src.p0 : (blockIdx.z == 1) ? src.p1 : src.p2;
    __half* o = dst + (size_t)blockIdx.z * n;
    size_t i = ((size_t)blockIdx.x * 256 + threadIdx.x) * 4;
    if (i >= n) return;
    float4 v = *reinterpret_cast<const float4*>(in + i);
    __half h[4];
    h[0] = __float2half_rn(v.x); h[1] = __float2half_rn(v.y);
    h[2] = __float2half_rn(v.z); h[3] = __float2half_rn(v.w);
    *reinterpret_cast<uint2*>(o + i) = *reinterpret_cast<const uint2*>(h);
}

// ---------------------------------------------------------------------------
// fp32 W[in,out] -> fp16 W^T[out,in], 3 weights in one launch (grid.z)
// ---------------------------------------------------------------------------
__global__ __launch_bounds__(256)
void transpose3_kernel(Src3 src, __half* __restrict__ dst, int R, int C)
{
    __shared__ float t[32][33];
    const float* in = (blockIdx.z == 0) ? src.p0 : (blockIdx.z == 1) ? src.p1 : src.p2;
    __half* oh = dst + (size_t)blockIdx.z * R * C;
    const int c0 = blockIdx.x * 32, r0 = blockIdx.y * 32;
    const int tx = threadIdx.x, ty = threadIdx.y;  // 32 x 8
#pragma unroll
    for (int j = 0; j < 4; ++j)
        t[ty + 8 * j][tx] = in[(size_t)(r0 + ty + 8 * j) * C + c0 + tx];
    __syncthreads();
#pragma unroll
    for (int j = 0; j < 4; ++j) {
        const size_t o = (size_t)(c0 + ty + 8 * j) * R + r0 + tx;
        oh[o] = __float2half_rn(t[tx][ty + 8 * j]);
    }
}

// ---------------------------------------------------------------------------
// In-place row softmax on fp16 (2048 cols), fp32 math, half2 vectorized
// ---------------------------------------------------------------------------
__inline__ __device__ float warp_max(float v) {
#pragma unroll
    for (int o = 16; o; o >>= 1) v = fmaxf(v, __shfl_xor_sync(0xFFFFFFFFu, v, o));
    return v;
}
__inline__ __device__ float warp_sum(float v) {
#pragma unroll
    for (int o = 16; o; o >>= 1) v += __shfl_xor_sync(0xFFFFFFFFu, v, o);
    return v;
}

__global__ __launch_bounds__(256)
void softmax_h_inplace_kernel(__half* __restrict__ P, int n)
{
    __shared__ float red[8];
    const size_t row = blockIdx.x;
    __half2* p2 = reinterpret_cast<__half2*>(P + row * (size_t)n);
    const int tid  = threadIdx.x;
    const int lane = tid & 31;
    const int warp = tid >> 5;

    float2 vals[4];
    float m = -INFINITY;
#pragma unroll
    for (int i = 0; i < 4; i++) {
        vals[i] = __half22float2(p2[tid + i * 256]);
        m = fmaxf(m, fmaxf(vals[i].x, vals[i].y));
    }
    m = warp_max(m);
    if (lane == 0) red[warp] = m;
    __syncthreads();
    if (warp == 0) {
        float x = (lane < 8) ? red[lane] : -INFINITY;
        x = warp_max(x);
        if (lane == 0) red[0] = x;
    }
    __syncthreads();
    m = red[0];
    __syncthreads();

    float s = 0.f;
#pragma unroll
    for (int i = 0; i < 4; i++) {
        vals[i].x = expf(vals[i].x - m);
        vals[i].y = expf(vals[i].y - m);
        s += vals[i].x + vals[i].y;
    }
    s = warp_sum(s);
    if (lane == 0) red[warp] = s;
    __syncthreads();
    if (warp == 0) {
        float x = (lane < 8) ? red[lane] : 0.f;
        x = warp_sum(x);
        if (lane == 0) red[0] = x;
    }
    __syncthreads();
    const float inv = 1.f / red[0];

#pragma unroll
    for (int i = 0; i < 4; i++) {
        float2 o = make_float2(vals[i].x * inv, vals[i].y * inv);
        p2[tid + i * 256] = __float22half2_rn(o);
    }
}

// ---------------------------------------------------------------------------
extern "C" void kernel_launch(void* const* d_in, const int* in_sizes, int n_in,
                              void* d_out, int out_size)
{
    const float* query = (const float*)d_in[0];
    const float* key   = (const float*)d_in[1];
    const float* value = (const float*)d_in[2];
    const float* Wq    = (const float*)d_in[3];
    const float* bq    = (const float*)d_in[4];
    const float* Wk    = (const float*)d_in[5];
    const float* bk    = (const float*)d_in[6];
    const float* Wv    = (const float*)d_in[7];
    const float* bv    = (const float*)d_in[8];
    float* out = (float*)d_out;

    __half *in16, *wt16, *qkv, *ph;
    float *bias3;
    cudaGetSymbolAddress((void**)&in16,  g_in);
    cudaGetSymbolAddress((void**)&wt16,  g_wt);
    cudaGetSymbolAddress((void**)&bias3, g_bias);
    cudaGetSymbolAddress((void**)&qkv,   g_qkv);
    cudaGetSymbolAddress((void**)&ph,    g_ph);

    cudaFuncSetAttribute(hgemm<2, true,  false>, cudaFuncAttributeMaxDynamicSharedMemorySize, SMEM_GEMM_K);
    cudaFuncSetAttribute(hgemm<2, false, false>, cudaFuncAttributeMaxDynamicSharedMemorySize, SMEM_GEMM_K);
    cudaFuncSetAttribute(hgemm<0, false, true >, cudaFuncAttributeMaxDynamicSharedMemorySize, SMEM_GEMM_T);

    // 0) biases -> contiguous slab (D2D async copies are graph-capturable)
    cudaMemcpyAsync(bias3 + 0 * EE, bq, EE * sizeof(float), cudaMemcpyDeviceToDevice);
    cudaMemcpyAsync(bias3 + 1 * EE, bk, EE * sizeof(float), cudaMemcpyDeviceToDevice);
    cudaMemcpyAsync(bias3 + 2 * EE, bv, EE * sizeof(float), cudaMemcpyDeviceToDevice);

    // 1) convert fp32 inputs -> fp16 slabs (one launch)
    {
        Src3 s{query, key, value};
        dim3 g((unsigned)(NBS / (256 * 4)), 1, 3);
        convert3_kernel<<<g, 256>>>(s, in16, NBS);
    }
    // 2) transpose weights -> fp16 W^T slabs (one launch)
    {
        Src3 s{Wq, Wk, Wv};
        dim3 g(EE / 32, EE / 32, 3), b(32, 8);
        transpose3_kernel<<<g, b>>>(s, wt16, EE, EE);
    }
    // 3) q,k,v projections in ONE launch (z strides over slabs)
    {
        dim3 g(EE / 128, (BB * SS) / 128, 3);
        hgemm<2, true, false><<<g, 256, SMEM_GEMM_K>>>(
            in16, wt16, bias3, nullptr, qkv,
            BB * SS, EE, EE,
            (long long)NBS, (long long)NW, (long long)NBS,
            EE, 1.0f);
    }
    // 4) scores: S = (q @ k^T) / 32, per batch -> fp16 g_ph
    {
        dim3 g(SS / 128, SS / 128, BB);
        hgemm<2, false, false><<<g, 256, SMEM_GEMM_K>>>(
            qkv /*q slab*/, qkv + NBS /*k slab*/, nullptr, nullptr, ph,
            SS, SS, EE,
            (long long)SS * EE, (long long)SS * EE, (long long)SS * SS,
            0, 1.0f / 32.0f);
    }
    // 5) softmax in-place on fp16
    softmax_h_inplace_kernel<<<BB * SS, 256>>>(ph, SS);
    // 6) out = P @ V (V row-major via TRANS_B), per batch -> d_out (fp32)
    {
        dim3 g(EE / 128, SS / 128, BB);
        hgemm<0, false, true><<<g, 256, SMEM_GEMM_T>>>(
            ph, qkv + 2 * NBS /*v slab [S,E]*/, nullptr, out, nullptr,
            SS, EE, SS,
            (long long)SS * SS, (long long)SS * EE, (long long)SS * EE,
            0, 1.0f);
    }
}

// round 16
// speedup vs baseline: 1.0038x; 1.0038x over previous
#include <cuda_runtime.h>
#include <cuda_fp16.h>
#include <math.h>
#include <stdint.h>

#define BB 4
#define SS 2048
#define EE 1024

#define NBS ((size_t)BB * SS * EE)   // 8388608
#define NW  ((size_t)EE * EE)        // 1048576
#define NP  ((size_t)BB * SS * SS)   // 16777216

// ---------------------------------------------------------------------------
// Scratch (__device__ globals) — contiguous slabs so grid.z can stride
// ---------------------------------------------------------------------------
__device__ __align__(256) __half g_in[3 * NBS];    // fp16 inputs   (q,k,v slabs)
__device__ __align__(256) __half g_wt[3 * NW];     // fp16 W^T      (q,k,v slabs)
__device__ __align__(256) float  g_bias[3 * EE];   // fp32 biases   (q,k,v slabs)
__device__ __align__(256) __half g_qkv[3 * NBS];   // fp16 q,k,v projections
__device__ __align__(256) __half g_ph[NP];         // fp16 scores -> probs (in-place)

struct Src3 { const float* p0; const float* p1; const float* p2; };

// ---------------------------------------------------------------------------
// Baseline-PTX primitives (compute_103-safe)
// ---------------------------------------------------------------------------
__device__ __forceinline__ uint32_t smem_u32(const void* p) {
    uint32_t a;
    asm("{ .reg .u64 t; cvta.to.shared.u64 t, %1; cvt.u32.u64 %0, t; }"
        : "=r"(a) : "l"(p));
    return a;
}

__device__ __forceinline__ void cp_async16(uint32_t s, const void* g) {
    asm volatile("cp.async.cg.shared.global [%0], [%1], 16;" :: "r"(s), "l"(g));
}
__device__ __forceinline__ void cp_commit() {
    asm volatile("cp.async.commit_group;" ::: "memory");
}
__device__ __forceinline__ void cp_wait1() {
    asm volatile("cp.async.wait_group 1;" ::: "memory");
}

__device__ __forceinline__ void ldsm4(uint32_t* r, uint32_t addr) {
    asm volatile("ldmatrix.sync.aligned.m8n8.x4.shared.b16 {%0,%1,%2,%3}, [%4];"
        : "=r"(r[0]), "=r"(r[1]), "=r"(r[2]), "=r"(r[3]) : "r"(addr));
}
__device__ __forceinline__ void ldsm4t(uint32_t* r, uint32_t addr) {
    asm volatile("ldmatrix.sync.aligned.m8n8.x4.trans.shared.b16 {%0,%1,%2,%3}, [%4];"
        : "=r"(r[0]), "=r"(r[1]), "=r"(r[2]), "=r"(r[3]) : "r"(addr));
}

__device__ __forceinline__ void mma16816(float* c, const uint32_t* a,
                                         const uint32_t* b) {
    asm volatile(
        "mma.sync.aligned.m16n8k16.row.col.f32.f16.f16.f32 "
        "{%0,%1,%2,%3}, {%4,%5,%6,%7}, {%8,%9}, {%0,%1,%2,%3};"
        : "+f"(c[0]), "+f"(c[1]), "+f"(c[2]), "+f"(c[3])
        : "r"(a[0]), "r"(a[1]), "r"(a[2]), "r"(a[3]), "r"(b[0]), "r"(b[1]));
}

// ---------------------------------------------------------------------------
// HMMA fp16 GEMM, 2 CTAs/SM, fragment-double-buffered inner loop.
//   TRANS_B = false: C = alpha*(A[M,K] @ B[N,K]^T)+bias  (B K-major)
//   TRANS_B = true : C = alpha*(A[M,K] @ B[K,N])+bias    (B N-major, e.g. V[S,E])
//   CTA 128x128, BK=64, 8 warps (2x4), warp tile 64x32, 3-stage cp.async.
//   OUT_MODE: 0 = fp32, 2 = fp16
// ---------------------------------------------------------------------------
#define ROWH 72                           // K-major pitch: 64 + 8 pad halves
#define TBPITCH 136                       // N-major pitch: 128 + 8 pad halves
#define TILE_A (128 * ROWH * 2)           // 18432 B
#define TILE_BK (128 * ROWH * 2)          // 18432 B
#define TILE_BT (64 * TBPITCH * 2)        // 17408 B

template <int OUT_MODE, bool HAS_BIAS, bool TRANS_B>
__global__ __launch_bounds__(256, 2)
void hgemm(const __half* __restrict__ A, const __half* __restrict__ B,
           const float* __restrict__ bias,
           float* __restrict__ Cf, __half* __restrict__ Ch,
           int M, int N, int K,
           long long sA, long long sB, long long sC,
           int biasStride, float alpha)
{
    constexpr int TILE_BSZ = TRANS_B ? TILE_BT : TILE_BK;
    constexpr int STAGE = TILE_A + TILE_BSZ;
    extern __shared__ __half sm[];
    const uint32_t sbase = smem_u32(sm);

    const int tid  = threadIdx.x;
    const int lane = tid & 31;
    const int wid  = tid >> 5;
    const int wm   = (wid >> 2) * 64;      // 0,64
    const int wn   = (wid & 3) * 32;       // 0..96

    const int n0 = blockIdx.x * 128;
    const int m0 = blockIdx.y * 128;

    A += (size_t)blockIdx.z * sA;
    B += (size_t)blockIdx.z * sB;
    if (HAS_BIAS) bias += (size_t)blockIdx.z * biasStride;

    const int nch = K >> 6;                // BK = 64

    auto issue_stage = [&](int c, int buf) {
        const int kt = c << 6;
        const uint32_t st = (uint32_t)buf * STAGE;
        // A: 128 rows x 8 chunks = 1024 chunks, 4/thread
#pragma unroll
        for (int it = 0; it < 4; ++it) {
            const int i = it * 256 + tid;
            const int r  = i >> 3;
            const int cm = i & 7;
            const __half* g = A + (size_t)(m0 + r) * K + kt + cm * 8;
            const uint32_t s = sbase + st + (uint32_t)r * (ROWH * 2)
                             + (uint32_t)cm * 16;
            cp_async16(s, g);
        }
        if (!TRANS_B) {
            // B: 128 n-rows x 8 chunks = 1024 chunks, 4/thread
#pragma unroll
            for (int it = 0; it < 4; ++it) {
                const int i = it * 256 + tid;
                const int r  = i >> 3;
                const int cm = i & 7;
                const __half* g = B + (size_t)(n0 + r) * K + kt + cm * 8;
                const uint32_t s = sbase + st + (uint32_t)TILE_A
                                 + (uint32_t)r * (ROWH * 2) + (uint32_t)cm * 16;
                cp_async16(s, g);
            }
        } else {
            // B: 64 k-rows x 16 chunks = 1024 chunks, 4/thread
#pragma unroll
            for (int it = 0; it < 4; ++it) {
                const int i = it * 256 + tid;
                const int r  = i >> 4;
                const int cm = i & 15;
                const __half* g = B + (size_t)(kt + r) * N + n0 + cm * 8;
                const uint32_t s = sbase + st + (uint32_t)TILE_A
                                 + (uint32_t)r * (TBPITCH * 2) + (uint32_t)cm * 16;
                cp_async16(s, g);
            }
        }
        cp_commit();
    };

    float acc[4][4][4];
#pragma unroll
    for (int i = 0; i < 4; ++i)
#pragma unroll
        for (int j = 0; j < 4; ++j)
#pragma unroll
            for (int q = 0; q < 4; ++q) acc[i][j][q] = 0.f;

    issue_stage(0, 0);
    issue_stage(1, 1);

    // fragment double buffers
    uint32_t ah[2][4][4];
    uint32_t bh[2][2][4];

    for (int c = 0; c < nch; ++c) {
        cp_wait1();
        __syncthreads();

        if (c + 2 < nch) issue_stage(c + 2, (c + 2) % 3);
        else             cp_commit();   // keep group counts aligned

        const uint32_t st = (uint32_t)(c % 3) * STAGE;
        const uint32_t sA_ = sbase + st;
        const uint32_t sB_ = sA_ + TILE_A;

        // per-thread invariant address components
        const uint32_t aAddr = sA_ + (uint32_t)(wm + (lane & 15)) * (ROWH * 2)
                             + (uint32_t)((lane >> 4) << 3) * 2;
        uint32_t bAddrK = 0, bAddrT = 0;
        if (!TRANS_B)
            bAddrK = sB_ + (uint32_t)(wn + ((lane >> 4) << 3) + (lane & 7)) * (ROWH * 2)
                   + (uint32_t)(((lane >> 3) & 1) << 3) * 2;
        else
            bAddrT = sB_ + (uint32_t)((((lane >> 3) & 1) << 3) + (lane & 7)) * (TBPITCH * 2)
                   + (uint32_t)(wn + ((lane >> 4) << 3)) * 2;

        auto load_a = [&](int buf, int ks) {
#pragma unroll
            for (int mi = 0; mi < 4; ++mi)
                ldsm4(ah[buf][mi], aAddr + (uint32_t)(mi * 16) * (ROWH * 2)
                                         + (uint32_t)ks * 2);
        };
        auto load_b = [&](int buf, int ks) {
            if (!TRANS_B) {
#pragma unroll
                for (int nb = 0; nb < 2; ++nb)
                    ldsm4(bh[buf][nb], bAddrK + (uint32_t)(nb * 16) * (ROWH * 2)
                                              + (uint32_t)ks * 2);
            } else {
#pragma unroll
                for (int nb = 0; nb < 2; ++nb)
                    ldsm4t(bh[buf][nb], bAddrT + (uint32_t)ks * (TBPITCH * 2)
                                               + (uint32_t)(nb * 16) * 2);
            }
        };

        load_a(0, 0);
        load_b(0, 0);

#pragma unroll
        for (int s = 0; s < 4; ++s) {
            const int cur = s & 1;
            const int nxt = cur ^ 1;
            if (s < 3) {                // prefetch next ks-step's fragments
                load_a(nxt, (s + 1) * 16);
                load_b(nxt, (s + 1) * 16);
            }
#pragma unroll
            for (int mi = 0; mi < 4; ++mi)
#pragma unroll
                for (int nf = 0; nf < 4; ++nf)
                    mma16816(acc[mi][nf], ah[cur][mi],
                             &bh[cur][nf >> 1][(nf & 1) << 1]);
        }
    }

    // ---- epilogue: each warp writes 64x32 ----
    const long long cbo = (long long)blockIdx.z * sC;
#pragma unroll
    for (int mi = 0; mi < 4; ++mi) {
        const int r0 = m0 + wm + mi * 16 + (lane >> 2);
#pragma unroll
        for (int nf = 0; nf < 4; ++nf) {
            const int col = n0 + wn + nf * 8 + (lane & 3) * 2;
            float b0 = 0.f, b1 = 0.f;
            if (HAS_BIAS) { b0 = __ldg(&bias[col]); b1 = __ldg(&bias[col + 1]); }
            const float v0 = acc[mi][nf][0] * alpha + b0;
            const float v1 = acc[mi][nf][1] * alpha + b1;
            const float v2 = acc[mi][nf][2] * alpha + b0;
            const float v3 = acc[mi][nf][3] * alpha + b1;
            const long long o0 = cbo + (long long)r0 * N + col;
            const long long o1 = o0 + 8LL * N;
            if (OUT_MODE == 0) {
                *reinterpret_cast<float2*>(Cf + o0) = make_float2(v0, v1);
                *reinterpret_cast<float2*>(Cf + o1) = make_float2(v2, v3);
            } else {
                *reinterpret_cast<__half2*>(Ch + o0) =
                    __halves2half2(__float2half_rn(v0), __float2half_rn(v1));
                *reinterpret_cast<__half2*>(Ch + o1) =
                    __halves2half2(__float2half_rn(v2), __float2half_rn(v3));
            }
        }
    }
}

#define SMEM_GEMM_K (3 * (TILE_A + TILE_BK))   // 110592 B
#define SMEM_GEMM_T (3 * (TILE_A + TILE_BT))   // 107520 B

// ---------------------------------------------------------------------------
// fp32 -> fp16 convert, 3 tensors in one launch (grid.z)
// ---------------------------------------------------------------------------
__global__ __launch_bounds__(256)
void convert3_kernel(Src3 src, __half* __restrict__ dst, size_t n)
{
    const float* in = (blockIdx.z == 0) ? src.p0 : (blockIdx.z == 1) ? src.p1 : src.p2;
    __half* o = dst + (size_t)blockIdx.z * n;
    size_t i = ((size_t)blockIdx.x * 256 + threadIdx.x) * 4;
    if (i >= n) return;
    float4 v = *reinterpret_cast<const float4*>(in + i);
    __half h[4];
    h[0] = __float2half_rn(v.x); h[1] = __float2half_rn(v.y);
    h[2] = __float2half_rn(v.z); h[3] = __float2half_rn(v.w);
    *reinterpret_cast<uint2*>(o + i) = *reinterpret_cast<const uint2*>(h);
}

// ---------------------------------------------------------------------------
// fp32 W[in,out] -> fp16 W^T[out,in], 3 weights in one launch (grid.z)
// ---------------------------------------------------------------------------
__global__ __launch_bounds__(256)
void transpose3_kernel(Src3 src, __half* __restrict__ dst, int R, int C)
{
    __shared__ float t[32][33];
    const float* in = (blockIdx.z == 0) ? src.p0 : (blockIdx.z == 1) ? src.p1 : src.p2;
    __half* oh = dst + (size_t)blockIdx.z * R * C;
    const int c0 = blockIdx.x * 32, r0 = blockIdx.y * 32;
    const int tx = threadIdx.x, ty = threadIdx.y;  // 32 x 8
#pragma unroll
    for (int j = 0; j < 4; ++j)
        t[ty + 8 * j][tx] = in[(size_t)(r0 + ty + 8 * j) * C + c0 + tx];
    __syncthreads();
#pragma unroll
    for (int j = 0; j < 4; ++j) {
        const size_t o = (size_t)(c0 + ty + 8 * j) * R + r0 + tx;
        oh[o] = __float2half_rn(t[tx][ty + 8 * j]);
    }
}

// ---------------------------------------------------------------------------
// In-place row softmax on fp16 (2048 cols), fp32 math, half2 vectorized
// ---------------------------------------------------------------------------
__inline__ __device__ float warp_max(float v) {
#pragma unroll
    for (int o = 16; o; o >>= 1) v = fmaxf(v, __shfl_xor_sync(0xFFFFFFFFu, v, o));
    return v;
}
__inline__ __device__ float warp_sum(float v) {
#pragma unroll
    for (int o = 16; o; o >>= 1) v += __shfl_xor_sync(0xFFFFFFFFu, v, o);
    return v;
}

__global__ __launch_bounds__(256)
void softmax_h_inplace_kernel(__half* __restrict__ P, int n)
{
    __shared__ float red[8];
    const size_t row = blockIdx.x;
    __half2* p2 = reinterpret_cast<__half2*>(P + row * (size_t)n);
    const int tid  = threadIdx.x;
    const int lane = tid & 31;
    const int warp = tid >> 5;

    float2 vals[4];
    float m = -INFINITY;
#pragma unroll
    for (int i = 0; i < 4; i++) {
        vals[i] = __half22float2(p2[tid + i * 256]);
        m = fmaxf(m, fmaxf(vals[i].x, vals[i].y));
    }
    m = warp_max(m);
    if (lane == 0) red[warp] = m;
    __syncthreads();
    if (warp == 0) {
        float x = (lane < 8) ? red[lane] : -INFINITY;
        x = warp_max(x);
        if (lane == 0) red[0] = x;
    }
    __syncthreads();
    m = red[0];
    __syncthreads();

    float s = 0.f;
#pragma unroll
    for (int i = 0; i < 4; i++) {
        vals[i].x = expf(vals[i].x - m);
        vals[i].y = expf(vals[i].y - m);
        s += vals[i].x + vals[i].y;
    }
    s = warp_sum(s);
    if (lane == 0) red[warp] = s;
    __syncthreads();
    if (warp == 0) {
        float x = (lane < 8) ? red[lane] : 0.f;
        x = warp_sum(x);
        if (lane == 0) red[0] = x;
    }
    __syncthreads();
    const float inv = 1.f / red[0];

#pragma unroll
    for (int i = 0; i < 4; i++) {
        float2 o = make_float2(vals[i].x * inv, vals[i].y * inv);
        p2[tid + i * 256] = __float22half2_rn(o);
    }
}

// ---------------------------------------------------------------------------
extern "C" void kernel_launch(void* const* d_in, const int* in_sizes, int n_in,
                              void* d_out, int out_size)
{
    const float* query = (const float*)d_in[0];
    const float* key   = (const float*)d_in[1];
    const float* value = (const float*)d_in[2];
    const float* Wq    = (const float*)d_in[3];
    const float* bq    = (const float*)d_in[4];
    const float* Wk    = (const float*)d_in[5];
    const float* bk    = (const float*)d_in[6];
    const float* Wv    = (const float*)d_in[7];
    const float* bv    = (const float*)d_in[8];
    float* out = (float*)d_out;

    __half *in16, *wt16, *qkv, *ph;
    float *bias3;
    cudaGetSymbolAddress((void**)&in16,  g_in);
    cudaGetSymbolAddress((void**)&wt16,  g_wt);
    cudaGetSymbolAddress((void**)&bias3, g_bias);
    cudaGetSymbolAddress((void**)&qkv,   g_qkv);
    cudaGetSymbolAddress((void**)&ph,    g_ph);

    cudaFuncSetAttribute(hgemm<2, true,  false>, cudaFuncAttributeMaxDynamicSharedMemorySize, SMEM_GEMM_K);
    cudaFuncSetAttribute(hgemm<2, false, false>, cudaFuncAttributeMaxDynamicSharedMemorySize, SMEM_GEMM_K);
    cudaFuncSetAttribute(hgemm<0, false, true >, cudaFuncAttributeMaxDynamicSharedMemorySize, SMEM_GEMM_T);

    // 0) biases -> contiguous slab (D2D async copies are graph-capturable)
    cudaMemcpyAsync(bias3 + 0 * EE, bq, EE * sizeof(float), cudaMemcpyDeviceToDevice);
    cudaMemcpyAsync(bias3 + 1 * EE, bk, EE * sizeof(float), cudaMemcpyDeviceToDevice);
    cudaMemcpyAsync(bias3 + 2 * EE, bv, EE * sizeof(float), cudaMemcpyDeviceToDevice);

    // 1) convert fp32 inputs -> fp16 slabs (one launch)
    {
        Src3 s{query, key, value};
        dim3 g((unsigned)(NBS / (256 * 4)), 1, 3);
        convert3_kernel<<<g, 256>>>(s, in16, NBS);
    }
    // 2) transpose weights -> fp16 W^T slabs (one launch)
    {
        Src3 s{Wq, Wk, Wv};
        dim3 g(EE / 32, EE / 32, 3), b(32, 8);
        transpose3_kernel<<<g, b>>>(s, wt16, EE, EE);
    }
    // 3) q,k,v projections in ONE launch (z strides over slabs)
    {
        dim3 g(EE / 128, (BB * SS) / 128, 3);
        hgemm<2, true, false><<<g, 256, SMEM_GEMM_K>>>(
            in16, wt16, bias3, nullptr, qkv,
            BB * SS, EE, EE,
            (long long)NBS, (long long)NW, (long long)NBS,
            EE, 1.0f);
    }
    // 4) scores: S = (q @ k^T) / 32, per batch -> fp16 g_ph
    {
        dim3 g(SS / 128, SS / 128, BB);
        hgemm<2, false, false><<<g, 256, SMEM_GEMM_K>>>(
            qkv /*q slab*/, qkv + NBS /*k slab*/, nullptr, nullptr, ph,
            SS, SS, EE,
            (long long)SS * EE, (long long)SS * EE, (long long)SS * SS,
            0, 1.0f / 32.0f);
    }
    // 5) softmax in-place on fp16
    softmax_h_inplace_kernel<<<BB * SS, 256>>>(ph, SS);
    // 6) out = P @ V (V row-major via TRANS_B), per batch -> d_out (fp32)
    {
        dim3 g(EE / 128, SS / 128, BB);
        hgemm<0, false, true><<<g, 256, SMEM_GEMM_T>>>(
            ph, qkv + 2 * NBS /*v slab [S,E]*/, nullptr, out, nullptr,
            SS, EE, SS,
            (long long)SS * SS, (long long)SS * EE, (long long)SS * EE,
            0, 1.0f);
    }
}